// round 15
// baseline (speedup 1.0000x reference)
#include <cuda_runtime.h>
#include <cstdint>

// Problem constants
#define N_NODES 2048
#define NF4     512             // N_NODES/4 float4 columns
#define K_TOTAL 3072            // B*L
#define KC      64              // k rows per reader task
#define NCHUNK  48              // k chunks (KC*NCHUNK == K_TOTAL)
#define NGRP    8               // node groups (64 f4-cols / 256 nodes each)
#define NREADER 192             // reader blocks (2 tasks each = 384 tasks)
#define NBLOCKS 256             // + 64 writer blocks (8 per group)
#define ROWS    3072

// Scratch + sync (device globals; counters protocol-reset to 0 every launch).
__device__ float g_part[NCHUNK * 8 * N_NODES];   // 3 MB partial conv sums
__device__ int   g_done[NGRP];                   // chunks finished per group
__device__ int   g_fin[NGRP];                    // writers finished per group

// ---- helpers ---------------------------------------------------------------
__device__ __forceinline__ float4 ldg4v(const float4* p) {
    float4 v;
    asm volatile("ld.global.nc.v4.f32 {%0,%1,%2,%3}, [%4];"
                 : "=f"(v.x), "=f"(v.y), "=f"(v.z), "=f"(v.w) : "l"(p));
    return v;
}
// COHERENT load (L2 path) — REQUIRED for data written by other blocks in the
// SAME kernel launch. .nc here returns stale lines (R14 bug).
__device__ __forceinline__ float ldg1_cg(const float* p) {
    float v;
    asm volatile("ld.global.cg.f32 %0, [%1];" : "=f"(v) : "l"(p));
    return v;
}
__device__ __forceinline__ unsigned long long pack2(float a, float b) {
    unsigned long long r;
    asm("mov.b64 %0, {%1, %2};" : "=l"(r) : "f"(a), "f"(b));
    return r;
}
__device__ __forceinline__ void fma2v(unsigned long long& d,
                                      unsigned long long a,
                                      unsigned long long b) {
    asm volatile("fma.rn.f32x2 %0, %1, %2, %0;" : "+l"(d) : "l"(a), "l"(b));
}
__device__ __forceinline__ void unpack2(unsigned long long v, float& a, float& b) {
    asm("mov.b64 {%0, %1}, %2;" : "=f"(a), "=f"(b) : "l"(v));
}

// ---------------------------------------------------------------------------
// Fused persistent kernel with block-role specialization.
// Readers (bid < 192): task t = bid + wave*192; group = t/48, chunk = t%48.
//   64 f4-cols x 64 k-rows per task (4 quarters of 16 rows, forced 8-deep
//   LDG.128 batches), quarter-reduced in SMEM, q0 stores partials (stcs),
//   threadfence + g_done[group]++.
// Writers (bid >= 192): 8 per group. Spin until the group's 48 chunks land,
//   then K2 (reduce 48 partials + folded MLP, 32 nodes) + K3 broadcast
//   (8 f4-cols x 3072 rows). Last writer per group resets the counters.
// Dependency is strictly reader -> writer: no deadlock at any residency.
// ---------------------------------------------------------------------------
__global__ __launch_bounds__(256, 2) void k_fused(
    const float4* __restrict__ x4, const float* __restrict__ Wc,
    const float* __restrict__ bc, const float* __restrict__ W1,
    const float* __restrict__ b1, const float* __restrict__ W2,
    const float* __restrict__ b2, float4* __restrict__ out)
{
    __shared__ alignas(16) float sWd[KC * 16];    // 4 KB reader weights (dup'd)
    __shared__ float4 sred[3 * 64 * 8];           // 24 KB quarter partials
    __shared__ float sWeff[256];                  // writer: folded W1
    __shared__ float sb1v[32], sW2v[32];
    __shared__ float sconv[8 * 33];               // writer: conv[j][n], padded
    __shared__ float spn[32];                     // writer: per-node scalars

    const int tid = threadIdx.x;
    const int bid = blockIdx.x;

    if (bid < NREADER) {
        // ================= READER =================
        const int ln = tid & 63;                  // f4-col in group
        const int q  = tid >> 6;                  // k quarter 0..3
        #pragma unroll 1
        for (int wave = 0; wave < 2; wave++) {
            const int t  = bid + wave * NREADER;  // 0..383, group-ordered
            const int g  = t / NCHUNK;            // 0..7
            const int ck = t % NCHUNK;            // 0..47
            const int k0 = ck * KC;

            const float* wsrc = Wc + (size_t)k0 * 8;
            #pragma unroll
            for (int i = tid; i < KC * 16; i += 256) sWd[i] = wsrc[i >> 1];
            __syncthreads();

            const int col = g * 64 + ln;
            const int kq  = q * 16;
            const float4* xp = x4 + (size_t)(k0 + kq) * NF4 + col;
            const ulonglong2* wp =
                reinterpret_cast<const ulonglong2*>(sWd) + (size_t)kq * 4;

            unsigned long long accp[2][8];
            #pragma unroll
            for (int p = 0; p < 2; p++)
                #pragma unroll
                for (int j = 0; j < 8; j++) accp[p][j] = 0ull;

            #pragma unroll
            for (int kk = 0; kk < 16; kk += 8) {
                float4 xv[8];
                #pragma unroll
                for (int u = 0; u < 8; u++)       // 8 LDG.128 back-to-back
                    xv[u] = ldg4v(xp + (size_t)(kk + u) * NF4);
                #pragma unroll
                for (int u = 0; u < 8; u++) {
                    unsigned long long lo = pack2(xv[u].x, xv[u].y);
                    unsigned long long hi = pack2(xv[u].z, xv[u].w);
                    const ulonglong2* w = wp + (kk + u) * 4;
                    #pragma unroll
                    for (int jj = 0; jj < 4; jj++) {
                        ulonglong2 wv = w[jj];
                        fma2v(accp[0][2 * jj],     lo, wv.x);
                        fma2v(accp[1][2 * jj],     hi, wv.x);
                        fma2v(accp[0][2 * jj + 1], lo, wv.y);
                        fma2v(accp[1][2 * jj + 1], hi, wv.y);
                    }
                }
            }

            if (q != 0) {
                float4* dst = sred + (size_t)(q - 1) * 64 * 8 + ln * 8;
                #pragma unroll
                for (int j = 0; j < 8; j++) {
                    float4 o;
                    unpack2(accp[0][j], o.x, o.y);
                    unpack2(accp[1][j], o.z, o.w);
                    dst[j] = o;
                }
            }
            __syncthreads();
            if (q == 0) {
                float4* gp4 = reinterpret_cast<float4*>(g_part);
                #pragma unroll
                for (int j = 0; j < 8; j++) {
                    float4 o;
                    unpack2(accp[0][j], o.x, o.y);
                    unpack2(accp[1][j], o.z, o.w);
                    #pragma unroll
                    for (int s = 0; s < 3; s++) {
                        float4 r = sred[(size_t)s * 64 * 8 + ln * 8 + j];
                        o.x += r.x; o.y += r.y; o.z += r.z; o.w += r.w;
                    }
                    __stcs(gp4 + (size_t)(ck * 8 + j) * NF4 + col, o);
                }
            }
            __threadfence();                      // partials visible chip-wide
            __syncthreads();                      // all threads' stores done
            if (tid == 0) atomicAdd(&g_done[g], 1);
        }
    } else {
        // ================= WRITER =================
        const int wi  = bid - NREADER;            // 0..63
        const int g   = wi >> 3;                  // group 0..7
        const int sub = wi & 7;                   // 0..7 within group

        // Preload MLP params while waiting.
        sWeff[tid] = W1[tid] + W1[tid + 256];
        if (tid < 32) { sb1v[tid] = b1[tid]; sW2v[tid] = W2[tid]; }

        if (tid == 0) {
            while (atomicAdd(&g_done[g], 0) < NCHUNK) __nanosleep(128);
            __threadfence();                      // acquire partials
        }
        __syncthreads();

        // K2: conv[j] for this block's 32 nodes. j = tid>>5, n = tid&31.
        // COHERENT .cg loads (data written by other blocks this launch).
        const int j  = tid >> 5;
        const int nl = tid & 31;
        const int n  = g * 256 + sub * 32 + nl;
        const float* pbase = g_part + (size_t)j * N_NODES + n;
        float conv = 0.0f;
        #pragma unroll
        for (int cb = 0; cb < NCHUNK; cb += 8) {
            float v[8];
            #pragma unroll
            for (int u = 0; u < 8; u++)
                v[u] = ldg1_cg(pbase + (size_t)(cb + u) * 8 * N_NODES);
            #pragma unroll
            for (int u = 0; u < 8; u++) conv += v[u];
        }
        conv += __ldg(bc + j);
        sconv[j * 33 + nl] = conv;
        __syncthreads();

        if (tid < 32) {                           // folded MLP, one node/thread
            float cv[8];
            #pragma unroll
            for (int jj = 0; jj < 8; jj++) cv[jj] = sconv[jj * 33 + tid];
            float pn = __ldg(b2);
            #pragma unroll 4
            for (int m = 0; m < 32; m++) {
                float h = sb1v[m];
                #pragma unroll
                for (int jj = 0; jj < 8; jj++)
                    h = fmaf(cv[jj], sWeff[jj * 32 + m], h);
                h = fmaxf(h, 0.01f * h);          // leaky_relu
                pn = fmaf(h, sW2v[m], pn);
            }
            spn[tid] = pn;
        }
        __syncthreads();

        // K3: broadcast this block's 8 f4-cols over all 3072 rows.
        const int cl  = tid & 7;                  // f4-col 0..7
        const int rs  = tid >> 3;                 // row phase 0..31
        const int cf4 = g * 64 + sub * 8 + cl;
        const float4 v = make_float4(spn[cl * 4 + 0], spn[cl * 4 + 1],
                                     spn[cl * 4 + 2], spn[cl * 4 + 3]);
        float4* obase = out + cf4;
        #pragma unroll 8
        for (int i = 0; i < 96; i++) {
            const int row = i * 32 + rs;
            obase[(size_t)row * NF4] = v;
        }

        __syncthreads();
        if (tid == 0) {                           // counter reset protocol
            int old = atomicAdd(&g_fin[g], 1);
            if (old == 7) {
                atomicExch(&g_done[g], 0);
                atomicExch(&g_fin[g], 0);
            }
        }
    }
}

// ---------------------------------------------------------------------------
// Inputs: 0:x 1:edge_index(unused) 2:edge_attr(unused) 3:Wc 4:bc 5:W1 6:b1 7:W2 8:b2
// ---------------------------------------------------------------------------
extern "C" void kernel_launch(void* const* d_in, const int* in_sizes, int n_in,
                              void* d_out, int out_size)
{
    const float4* x4 = (const float4*)d_in[0];
    const float*  Wc = (const float*)d_in[3];
    const float*  bc = (const float*)d_in[4];
    const float*  W1 = (const float*)d_in[5];
    const float*  b1 = (const float*)d_in[6];
    const float*  W2 = (const float*)d_in[7];
    const float*  b2 = (const float*)d_in[8];
    float* out = (float*)d_out;

    k_fused<<<NBLOCKS, 256>>>(x4, Wc, bc, W1, b1, W2, b2,
                              reinterpret_cast<float4*>(out));
}

// round 16
// speedup vs baseline: 1.3063x; 1.3063x over previous
#include <cuda_runtime.h>
#include <cstdint>

// Problem constants
#define N_NODES 2048
#define NF4     512             // N_NODES/4 float4 columns
#define K_TOTAL 3072            // B*L
#define KC      128             // k rows per block chunk
#define NKC     24              // chunks (KC*NKC == K_TOTAL)
#define NBN     8               // n blocks (64 f4-cols each)
#define ROWS    3072

// Scratch device globals. g_conv is zeroed by k_zero each launch, accumulated
// by k_gemm (red.global.add), consumed by k_mlp_bcast.
__device__ float g_conv[8 * N_NODES];         // 64 KB conv accumulators

// ---- helpers ---------------------------------------------------------------
__device__ __forceinline__ float4 ldg4v(const float4* p) {
    float4 v;
    asm volatile("ld.global.nc.v4.f32 {%0,%1,%2,%3}, [%4];"
                 : "=f"(v.x), "=f"(v.y), "=f"(v.z), "=f"(v.w) : "l"(p));
    return v;
}
__device__ __forceinline__ float ldg1_cg(const float* p) {
    float v;
    asm volatile("ld.global.cg.f32 %0, [%1];" : "=f"(v) : "l"(p));
    return v;
}
__device__ __forceinline__ void red_add(float* p, float v) {
    asm volatile("red.global.add.f32 [%0], %1;" :: "l"(p), "f"(v) : "memory");
}
__device__ __forceinline__ unsigned long long pack2(float a, float b) {
    unsigned long long r;
    asm("mov.b64 %0, {%1, %2};" : "=l"(r) : "f"(a), "f"(b));
    return r;
}
__device__ __forceinline__ void fma2v(unsigned long long& d,
                                      unsigned long long a,
                                      unsigned long long b) {
    asm volatile("fma.rn.f32x2 %0, %1, %2, %0;" : "+l"(d) : "l"(a), "l"(b));
}
__device__ __forceinline__ void unpack2(unsigned long long v, float& a, float& b) {
    asm("mov.b64 {%0, %1}, %2;" : "=f"(a), "=f"(b) : "l"(v));
}

// ---------------------------------------------------------------------------
// K0: zero the conv accumulators (64 KB). grid = 16 x 256, one f4 each.
// ---------------------------------------------------------------------------
__global__ __launch_bounds__(256) void k_zero()
{
    float4* c4 = reinterpret_cast<float4*>(g_conv);
    c4[blockIdx.x * 256 + threadIdx.x] = make_float4(0.f, 0.f, 0.f, 0.f);
}

// ---------------------------------------------------------------------------
// K1: skinny GEMM (proven R4 recipe). Block = 64 f4-cols x 4 k-quarters
// (KC=128 rows). Thread: one f4 column over 32 k-rows, forced 8-deep LDG.128
// batches. Quarters reduced in SMEM; q0 accumulates into g_conv via REDG
// (no partials round-trip). grid = (8,24) x 256.
// ---------------------------------------------------------------------------
__global__ __launch_bounds__(256, 2) void k_gemm(
    const float4* __restrict__ x4, const float* __restrict__ Wc)
{
    __shared__ alignas(16) float sWd[KC * 8 * 2];    // 8 KB: Wc dup'd pairs
    __shared__ float4 sred[3 * 64 * 8];              // 24 KB: quarter partials

    const int tid  = threadIdx.x;
    const int ln   = tid & 63;
    const int q    = tid >> 6;
    const int nblk = blockIdx.x;
    const int kblk = blockIdx.y;

    const float* wsrc = Wc + (size_t)kblk * KC * 8;
    #pragma unroll
    for (int i = tid; i < KC * 8 * 2; i += 256) sWd[i] = wsrc[i >> 1];
    __syncthreads();

    const int c  = nblk * 64 + ln;
    const int kq = q * 32;
    const float4* xp = x4 + ((size_t)kblk * KC + kq) * NF4 + c;
    const ulonglong2* wp =
        reinterpret_cast<const ulonglong2*>(sWd) + (size_t)kq * 4;

    unsigned long long accp[2][8];
    #pragma unroll
    for (int p = 0; p < 2; p++)
        #pragma unroll
        for (int j = 0; j < 8; j++) accp[p][j] = 0ull;

    #pragma unroll
    for (int kk = 0; kk < 32; kk += 8) {
        float4 xv[8];
        #pragma unroll
        for (int u = 0; u < 8; u++)                  // 8 LDG.128 back-to-back
            xv[u] = ldg4v(xp + (size_t)(kk + u) * NF4);
        #pragma unroll
        for (int u = 0; u < 8; u++) {
            unsigned long long lo = pack2(xv[u].x, xv[u].y);
            unsigned long long hi = pack2(xv[u].z, xv[u].w);
            const ulonglong2* w = wp + (kk + u) * 4;
            #pragma unroll
            for (int jj = 0; jj < 4; jj++) {
                ulonglong2 wv = w[jj];               // LDS.128: two j weights
                fma2v(accp[0][2 * jj],     lo, wv.x);
                fma2v(accp[1][2 * jj],     hi, wv.x);
                fma2v(accp[0][2 * jj + 1], lo, wv.y);
                fma2v(accp[1][2 * jj + 1], hi, wv.y);
            }
        }
    }

    if (q != 0) {
        float4* dst = sred + (size_t)(q - 1) * 64 * 8 + ln * 8;
        #pragma unroll
        for (int j = 0; j < 8; j++) {
            float4 o;
            unpack2(accp[0][j], o.x, o.y);
            unpack2(accp[1][j], o.z, o.w);
            dst[j] = o;
        }
    }
    __syncthreads();
    if (q == 0) {
        #pragma unroll
        for (int j = 0; j < 8; j++) {
            float4 o;
            unpack2(accp[0][j], o.x, o.y);
            unpack2(accp[1][j], o.z, o.w);
            #pragma unroll
            for (int s = 0; s < 3; s++) {
                float4 r = sred[(size_t)s * 64 * 8 + ln * 8 + j];
                o.x += r.x; o.y += r.y; o.z += r.z; o.w += r.w;
            }
            float* cp = g_conv + (size_t)j * N_NODES + 4 * c;
            red_add(cp + 0, o.x);
            red_add(cp + 1, o.y);
            red_add(cp + 2, o.z);
            red_add(cp + 3, o.w);
        }
    }
}

// ---------------------------------------------------------------------------
// K3': fused MLP + broadcast. Block = 8 f4-cols (32 nodes) x 512 rows.
// grid = 384 (64 col-groups x 6 row-groups) x 256 threads.
// Each block reads its 256 conv values from L2, folds the MLP for its 32
// nodes (x6 redundancy across row-groups — trivial), then streams its slab.
// ---------------------------------------------------------------------------
__global__ __launch_bounds__(256) void k_mlp_bcast(
    const float* __restrict__ bc, const float* __restrict__ W1,
    const float* __restrict__ b1, const float* __restrict__ W2,
    const float* __restrict__ b2, float4* __restrict__ out)
{
    __shared__ float sWeff[256];          // folded W1
    __shared__ float sb1v[32], sW2v[32];
    __shared__ float sconv[8 * 33];       // conv[j][node], padded
    __shared__ float spn[32];             // per-node scalars

    const int tid = threadIdx.x;
    const int cg  = blockIdx.x & 63;      // col group 0..63
    const int rg  = blockIdx.x >> 6;      // row group 0..5

    sWeff[tid] = W1[tid] + W1[tid + 256];
    if (tid < 32) { sb1v[tid] = b1[tid]; sW2v[tid] = W2[tid]; }

    // Load this col-group's conv values (+ bias): j = tid>>5, node = cg*32+(tid&31)
    {
        const int j  = tid >> 5;
        const int nl = tid & 31;
        float v = ldg1_cg(g_conv + (size_t)j * N_NODES + cg * 32 + nl);
        sconv[j * 33 + nl] = v + __ldg(bc + j);
    }
    __syncthreads();

    if (tid < 32) {                       // folded MLP, one node per thread
        float cv[8];
        #pragma unroll
        for (int jj = 0; jj < 8; jj++) cv[jj] = sconv[jj * 33 + tid];
        float pn = __ldg(b2);
        #pragma unroll 4
        for (int m = 0; m < 32; m++) {
            float h = sb1v[m];
            #pragma unroll
            for (int jj = 0; jj < 8; jj++)
                h = fmaf(cv[jj], sWeff[jj * 32 + m], h);
            h = fmaxf(h, 0.01f * h);      // leaky_relu
            pn = fmaf(h, sW2v[m], pn);
        }
        spn[tid] = pn;
    }
    __syncthreads();

    // Broadcast: col = cg*8 + (tid&7); rows rg*512 + (tid>>3) + i*32.
    const int c7  = tid & 7;
    const int cf4 = cg * 8 + c7;
    const float4 v = make_float4(spn[c7 * 4 + 0], spn[c7 * 4 + 1],
                                 spn[c7 * 4 + 2], spn[c7 * 4 + 3]);
    float4* obase = out + (size_t)(rg * 512 + (tid >> 3)) * NF4 + cf4;
    #pragma unroll
    for (int i = 0; i < 16; i++)
        obase[(size_t)i * 32 * NF4] = v;
}

// ---------------------------------------------------------------------------
// Inputs: 0:x 1:edge_index(unused) 2:edge_attr(unused) 3:Wc 4:bc 5:W1 6:b1 7:W2 8:b2
// ---------------------------------------------------------------------------
extern "C" void kernel_launch(void* const* d_in, const int* in_sizes, int n_in,
                              void* d_out, int out_size)
{
    const float4* x4 = (const float4*)d_in[0];
    const float*  Wc = (const float*)d_in[3];
    const float*  bc = (const float*)d_in[4];
    const float*  W1 = (const float*)d_in[5];
    const float*  b1 = (const float*)d_in[6];
    const float*  W2 = (const float*)d_in[7];
    const float*  b2 = (const float*)d_in[8];
    float* out = (float*)d_out;

    k_zero<<<16, 256>>>();
    k_gemm<<<dim3(NBN, NKC), 256>>>(x4, Wc);
    k_mlp_bcast<<<384, 256>>>(bc, W1, b1, W2, b2,
                              reinterpret_cast<float4*>(out));
}

// round 17
// speedup vs baseline: 1.4414x; 1.1034x over previous
#include <cuda_runtime.h>
#include <cstdint>

// Problem constants
#define N_NODES 2048
#define NF4     512             // N_NODES/4 float4 columns
#define K_TOTAL 3072            // B*L
#define KC      128             // k rows per block chunk
#define NKC     24              // chunks (KC*NKC == K_TOTAL)
#define NBN     8               // n blocks (64 f4-cols each)
#define ROWS    3072

// Scratch (device global; fully overwritten every launch — no init needed).
__device__ float g_part[NKC * 8 * N_NODES];   // 1.5 MB partial conv sums

// ---- helpers ---------------------------------------------------------------
__device__ __forceinline__ float4 ldg4v(const float4* p) {
    float4 v;
    asm volatile("ld.global.nc.v4.f32 {%0,%1,%2,%3}, [%4];"
                 : "=f"(v.x), "=f"(v.y), "=f"(v.z), "=f"(v.w) : "l"(p));
    return v;
}
__device__ __forceinline__ float ldg1v(const float* p) {
    float v;
    asm volatile("ld.global.nc.f32 %0, [%1];" : "=f"(v) : "l"(p));
    return v;
}
__device__ __forceinline__ unsigned long long pack2(float a, float b) {
    unsigned long long r;
    asm("mov.b64 %0, {%1, %2};" : "=l"(r) : "f"(a), "f"(b));
    return r;
}
__device__ __forceinline__ void fma2v(unsigned long long& d,
                                      unsigned long long a,
                                      unsigned long long b) {
    asm volatile("fma.rn.f32x2 %0, %1, %2, %0;" : "+l"(d) : "l"(a), "l"(b));
}
__device__ __forceinline__ void unpack2(unsigned long long v, float& a, float& b) {
    asm("mov.b64 {%0, %1}, %2;" : "=f"(a), "=f"(b) : "l"(v));
}

// ---------------------------------------------------------------------------
// K1: skinny GEMM (proven R4 recipe, 12.0us). Block = 64 f4-cols x 4
// k-quarters (KC=128 rows). Thread: one f4 column over 32 k-rows, forced
// 8-deep LDG.128 batches. Quarters reduced in SMEM; q0 stores partials.
// grid = (8,24) x 256.
// ---------------------------------------------------------------------------
__global__ __launch_bounds__(256, 2) void k_gemm(
    const float4* __restrict__ x4, const float* __restrict__ Wc)
{
    __shared__ alignas(16) float sWd[KC * 8 * 2];    // 8 KB: Wc dup'd pairs
    __shared__ float4 sred[3 * 64 * 8];              // 24 KB: quarter partials

    const int tid  = threadIdx.x;
    const int ln   = tid & 63;
    const int q    = tid >> 6;
    const int nblk = blockIdx.x;
    const int kblk = blockIdx.y;

    const float* wsrc = Wc + (size_t)kblk * KC * 8;
    #pragma unroll
    for (int i = tid; i < KC * 8 * 2; i += 256) sWd[i] = wsrc[i >> 1];
    __syncthreads();

    const int c  = nblk * 64 + ln;
    const int kq = q * 32;
    const float4* xp = x4 + ((size_t)kblk * KC + kq) * NF4 + c;
    const ulonglong2* wp =
        reinterpret_cast<const ulonglong2*>(sWd) + (size_t)kq * 4;

    unsigned long long accp[2][8];
    #pragma unroll
    for (int p = 0; p < 2; p++)
        #pragma unroll
        for (int j = 0; j < 8; j++) accp[p][j] = 0ull;

    #pragma unroll
    for (int kk = 0; kk < 32; kk += 8) {
        float4 xv[8];
        #pragma unroll
        for (int u = 0; u < 8; u++)                  // 8 LDG.128 back-to-back
            xv[u] = ldg4v(xp + (size_t)(kk + u) * NF4);
        #pragma unroll
        for (int u = 0; u < 8; u++) {
            unsigned long long lo = pack2(xv[u].x, xv[u].y);
            unsigned long long hi = pack2(xv[u].z, xv[u].w);
            const ulonglong2* w = wp + (kk + u) * 4;
            #pragma unroll
            for (int jj = 0; jj < 4; jj++) {
                ulonglong2 wv = w[jj];               // LDS.128: two j weights
                fma2v(accp[0][2 * jj],     lo, wv.x);
                fma2v(accp[1][2 * jj],     hi, wv.x);
                fma2v(accp[0][2 * jj + 1], lo, wv.y);
                fma2v(accp[1][2 * jj + 1], hi, wv.y);
            }
        }
    }

    if (q != 0) {
        float4* dst = sred + (size_t)(q - 1) * 64 * 8 + ln * 8;
        #pragma unroll
        for (int j = 0; j < 8; j++) {
            float4 o;
            unpack2(accp[0][j], o.x, o.y);
            unpack2(accp[1][j], o.z, o.w);
            dst[j] = o;
        }
    }
    __syncthreads();
    if (q == 0) {
        float4* gp4 = reinterpret_cast<float4*>(g_part);
        #pragma unroll
        for (int j = 0; j < 8; j++) {
            float4 o;
            unpack2(accp[0][j], o.x, o.y);
            unpack2(accp[1][j], o.z, o.w);
            #pragma unroll
            for (int s = 0; s < 3; s++) {
                float4 r = sred[(size_t)s * 64 * 8 + ln * 8 + j];
                o.x += r.x; o.y += r.y; o.z += r.z; o.w += r.w;
            }
            __stcs(gp4 + (size_t)(kblk * 8 + j) * NF4 + c, o);
        }
    }
}

// ---------------------------------------------------------------------------
// K2+K3 fused: reduce + MLP + broadcast in one kernel.
// Block = (cg: 32 nodes) x (rg: 512 rows); grid = 384 (64 x 6) x 256.
// Each block re-reduces its 24 partials from L2 (6KB; x6 redundancy is
// hidden under the store stream), folds the MLP for its 32 nodes, then
// streams its 512-row x 8-f4col output slab.
// Partials were written by the PREVIOUS kernel launch (L1 flushed at the
// boundary), so .nc reads are coherent here.
// ---------------------------------------------------------------------------
__global__ __launch_bounds__(256) void k_mlp_bcast(
    const float* __restrict__ bc, const float* __restrict__ W1,
    const float* __restrict__ b1, const float* __restrict__ W2,
    const float* __restrict__ b2, float4* __restrict__ out)
{
    __shared__ float sWeff[256];          // folded W1
    __shared__ float sb1v[32], sW2v[32];
    __shared__ float sconv[8 * 33];       // conv[j][node], padded
    __shared__ float spn[32];             // per-node scalars

    const int tid = threadIdx.x;
    const int cg  = blockIdx.x & 63;      // col group 0..63 (32 nodes)
    const int rg  = blockIdx.x >> 6;      // row group 0..5 (512 rows)

    sWeff[tid] = W1[tid] + W1[tid + 256];
    if (tid < 32) { sb1v[tid] = b1[tid]; sW2v[tid] = W2[tid]; }

    // Reduce 24 partials for this block's nodes: j = tid>>5, nl = tid&31.
    {
        const int j  = tid >> 5;
        const int nl = tid & 31;
        const float* pbase = g_part + (size_t)j * N_NODES + cg * 32 + nl;
        float conv = 0.0f;
        #pragma unroll
        for (int kc = 0; kc < NKC; kc += 8) {
            float v[8];
            #pragma unroll
            for (int u = 0; u < 8; u++)
                v[u] = ldg1v(pbase + (size_t)(kc + u) * 8 * N_NODES);
            #pragma unroll
            for (int u = 0; u < 8; u++) conv += v[u];
        }
        sconv[j * 33 + nl] = conv + __ldg(bc + j);
    }
    __syncthreads();

    if (tid < 32) {                       // folded MLP, one node per thread
        float cv[8];
        #pragma unroll
        for (int jj = 0; jj < 8; jj++) cv[jj] = sconv[jj * 33 + tid];
        float pn = __ldg(b2);
        #pragma unroll 4
        for (int m = 0; m < 32; m++) {
            float h = sb1v[m];
            #pragma unroll
            for (int jj = 0; jj < 8; jj++)
                h = fmaf(cv[jj], sWeff[jj * 32 + m], h);
            h = fmaxf(h, 0.01f * h);      // leaky_relu
            pn = fmaf(h, sW2v[m], pn);
        }
        spn[tid] = pn;
    }
    __syncthreads();

    // Broadcast: col = cg*8 + (tid&7); rows rg*512 + (tid>>3) + i*32.
    const int c7  = tid & 7;
    const int cf4 = cg * 8 + c7;
    const float4 v = make_float4(spn[c7 * 4 + 0], spn[c7 * 4 + 1],
                                 spn[c7 * 4 + 2], spn[c7 * 4 + 3]);
    float4* obase = out + (size_t)(rg * 512 + (tid >> 3)) * NF4 + cf4;
    #pragma unroll
    for (int i = 0; i < 16; i++)
        obase[(size_t)i * 32 * NF4] = v;
}

// ---------------------------------------------------------------------------
// Inputs: 0:x 1:edge_index(unused) 2:edge_attr(unused) 3:Wc 4:bc 5:W1 6:b1 7:W2 8:b2
// ---------------------------------------------------------------------------
extern "C" void kernel_launch(void* const* d_in, const int* in_sizes, int n_in,
                              void* d_out, int out_size)
{
    const float4* x4 = (const float4*)d_in[0];
    const float*  Wc = (const float*)d_in[3];
    const float*  bc = (const float*)d_in[4];
    const float*  W1 = (const float*)d_in[5];
    const float*  b1 = (const float*)d_in[6];
    const float*  W2 = (const float*)d_in[7];
    const float*  b2 = (const float*)d_in[8];
    float* out = (float*)d_out;

    k_gemm<<<dim3(NBN, NKC), 256>>>(x4, Wc);
    k_mlp_bcast<<<384, 256>>>(bc, W1, b1, W2, b2,
                              reinterpret_cast<float4*>(out));
}